// round 1
// baseline (speedup 1.0000x reference)
#include <cuda_runtime.h>
#include <cuda_bf16.h>
#include <math.h>

// Problem constants (fixed shapes for this problem)
#define NMAX 100000
#define EMAX 1600000
#define CIN  128
#define CO   64
#define CH   128   // combined channels: [0..63]=mu, [64..127]=logstd

// ---------------- scratch (static device globals; no runtime alloc) --------
__device__ int   g_is64;
__device__ int   g_src[EMAX];
__device__ int   g_dst[EMAX];
__device__ float g_deg[NMAX];
__device__ float g_dinv[NMAX];
__device__ float g_h[(size_t)NMAX * CH];    // 51.2 MB
__device__ float g_acc[(size_t)NMAX * CH];  // 51.2 MB

// ---------------- dtype detection: int64 vs int32 edge_index ---------------
// If the buffer is little-endian int64 with values in [0, N), every odd
// 32-bit word is zero. If it's int32 random indices, odd words are almost
// surely nonzero. Scan first 2048 words.
__global__ void detect_kernel(const unsigned int* __restrict__ w, int nwords) {
    __shared__ int any;
    if (threadIdx.x == 0) any = 0;
    __syncthreads();
    int local = 0;
    for (int i = 1 + 2 * threadIdx.x; i < nwords; i += 2 * blockDim.x)
        local |= (w[i] != 0u);
    if (local) atomicOr(&any, 1);
    __syncthreads();
    if (threadIdx.x == 0) g_is64 = (any == 0) ? 1 : 0;
}

// ---------------- init: deg = 1 (self loop), acc = 0 -----------------------
__global__ void init_kernel(int n_acc4, int n_nodes) {
    int i = blockIdx.x * blockDim.x + threadIdx.x;
    if (i < n_acc4) {
        ((float4*)g_acc)[i] = make_float4(0.f, 0.f, 0.f, 0.f);
    }
    if (i < n_nodes) {
        g_deg[i] = 1.0f;
    }
}

// ---------------- convert indices + degree histogram -----------------------
__global__ void convert_kernel(const void* __restrict__ ei, int E) {
    int e = blockIdx.x * blockDim.x + threadIdx.x;
    if (e >= E) return;
    int s, d;
    if (g_is64) {
        const long long* p = (const long long*)ei;
        s = (int)p[e];
        d = (int)p[e + E];
    } else {
        const int* p = (const int*)ei;
        s = p[e];
        d = p[e + E];
    }
    g_src[e] = s;
    g_dst[e] = d;
    atomicAdd(&g_deg[d], 1.0f);
}

__global__ void dinv_kernel(int n_nodes) {
    int i = blockIdx.x * blockDim.x + threadIdx.x;
    if (i < n_nodes) g_dinv[i] = rsqrtf(g_deg[i]);
}

// ---------------- fused GEMM: h = x @ [W_mu | W_ls] ------------------------
// Tile: 64 rows x 128 cols, K-chunks of 32. 256 threads, each computes 4x8.
__global__ __launch_bounds__(256) void gemm_kernel(
    const float* __restrict__ x,
    const float* __restrict__ Wmu,
    const float* __restrict__ Wls,
    int n_nodes)
{
    __shared__ float xs[64][36];   // padded to avoid bank conflicts
    __shared__ float ws[32][CH];

    int block_row = blockIdx.x * 64;
    int tid = threadIdx.x;
    int tx = tid & 15;   // col group: 8 cols each
    int ty = tid >> 4;   // row group: 4 rows each

    float acc[4][8];
#pragma unroll
    for (int r = 0; r < 4; r++)
#pragma unroll
        for (int c = 0; c < 8; c++) acc[r][c] = 0.f;

    for (int kk = 0; kk < CIN; kk += 32) {
        // load x tile: 64x32 floats, 2 float4 per thread
#pragma unroll
        for (int i = 0; i < 2; i++) {
            int f  = tid * 2 + i;        // float4 id 0..511
            int r  = f >> 3;             // 8 float4 per row
            int c4 = (f & 7) * 4;
            int grow = block_row + r;
            float4 v = make_float4(0.f, 0.f, 0.f, 0.f);
            if (grow < n_nodes)
                v = *(const float4*)&x[(size_t)grow * CIN + kk + c4];
            xs[r][c4 + 0] = v.x;
            xs[r][c4 + 1] = v.y;
            xs[r][c4 + 2] = v.z;
            xs[r][c4 + 3] = v.w;
        }
        // load W tile: 32x128 floats, 4 float4 per thread
#pragma unroll
        for (int i = 0; i < 4; i++) {
            int f    = tid * 4 + i;      // float4 id 0..1023
            int r    = f >> 5;           // 32 float4 per row
            int col0 = (f & 31) * 4;
            int k    = kk + r;
            float4 v;
            if (col0 < CO) v = *(const float4*)&Wmu[k * CO + col0];
            else           v = *(const float4*)&Wls[k * CO + (col0 - CO)];
            *(float4*)&ws[r][col0] = v;
        }
        __syncthreads();

#pragma unroll
        for (int k = 0; k < 32; k++) {
            float a[4], b[8];
#pragma unroll
            for (int r = 0; r < 4; r++) a[r] = xs[ty * 4 + r][k];
            float4 b0 = *(const float4*)&ws[k][tx * 8];
            float4 b1 = *(const float4*)&ws[k][tx * 8 + 4];
            b[0] = b0.x; b[1] = b0.y; b[2] = b0.z; b[3] = b0.w;
            b[4] = b1.x; b[5] = b1.y; b[6] = b1.z; b[7] = b1.w;
#pragma unroll
            for (int r = 0; r < 4; r++)
#pragma unroll
                for (int c = 0; c < 8; c++)
                    acc[r][c] = fmaf(a[r], b[c], acc[r][c]);
        }
        __syncthreads();
    }

    // store h
#pragma unroll
    for (int r = 0; r < 4; r++) {
        int grow = block_row + ty * 4 + r;
        if (grow >= n_nodes) continue;
        float* out = &g_h[(size_t)grow * CH + tx * 8];
        float4 o0 = make_float4(acc[r][0], acc[r][1], acc[r][2], acc[r][3]);
        float4 o1 = make_float4(acc[r][4], acc[r][5], acc[r][6], acc[r][7]);
        *(float4*)out       = o0;
        *(float4*)(out + 4) = o1;
    }
}

// ---------------- edge scatter: one warp per edge, float4 atomics ----------
__global__ __launch_bounds__(256) void scatter_kernel(int E) {
    int gw   = (blockIdx.x * blockDim.x + threadIdx.x) >> 5;
    int lane = threadIdx.x & 31;
    if (gw >= E) return;
    int s = g_src[gw];
    int d = g_dst[gw];
    float norm = g_dinv[s] * g_dinv[d];
    float4 v = *(const float4*)&g_h[(size_t)s * CH + lane * 4];
    v.x *= norm; v.y *= norm; v.z *= norm; v.w *= norm;
    atomicAdd((float4*)&g_acc[(size_t)d * CH + lane * 4], v);
}

// ---------------- epilogue: self-loop + bias + reparameterization ----------
__global__ void final_kernel(const float* __restrict__ bmu,
                             const float* __restrict__ bls,
                             const float* __restrict__ eps,
                             float* __restrict__ z,
                             int n_nodes)
{
    int i = blockIdx.x * blockDim.x + threadIdx.x;
    if (i >= n_nodes * CO) return;
    int n = i >> 6;
    int c = i & 63;
    float dv = g_dinv[n];
    float d2 = dv * dv;               // self-loop norm = 1/deg
    size_t base = (size_t)n * CH;
    float mu = g_acc[base + c]      + g_h[base + c]      * d2 + bmu[c];
    float ls = g_acc[base + CO + c] + g_h[base + CO + c] * d2 + bls[c];
    ls = fminf(ls, 10.0f);
    z[i] = fmaf(eps[i], expf(ls), mu);
}

// ---------------------------------------------------------------------------
extern "C" void kernel_launch(void* const* d_in, const int* in_sizes, int n_in,
                              void* d_out, int out_size) {
    const float* x    = (const float*)d_in[0];
    const void*  ei   = (const void*)d_in[1];
    const float* Wmu  = (const float*)d_in[2];
    const float* bmu  = (const float*)d_in[3];
    const float* Wls  = (const float*)d_in[4];
    const float* bls  = (const float*)d_in[5];
    const float* eps  = (const float*)d_in[6];
    float* z = (float*)d_out;

    int N = in_sizes[0] / CIN;          // 100000
    int E = in_sizes[1] / 2;            // 1600000

    // 1) dtype detection for edge_index (int64 vs int32)
    int nwords = 2048;
    detect_kernel<<<1, 256>>>((const unsigned int*)ei, nwords);

    // 2) init deg=1, acc=0
    int n_acc4 = (N * CH) / 4;
    int init_threads = (n_acc4 > N) ? n_acc4 : N;
    init_kernel<<<(init_threads + 255) / 256, 256>>>(n_acc4, N);

    // 3) convert indices + degree histogram
    convert_kernel<<<(E + 255) / 256, 256>>>(ei, E);

    // 4) dinv
    dinv_kernel<<<(N + 255) / 256, 256>>>(N);

    // 5) fused GEMM h = x @ [W_mu | W_ls]
    gemm_kernel<<<(N + 63) / 64, 256>>>(x, Wmu, Wls, N);

    // 6) edge scatter (both convs fused, one warp per edge)
    {
        int warps_per_block = 256 / 32;
        int blocks = (E + warps_per_block - 1) / warps_per_block;
        scatter_kernel<<<blocks, 256>>>(E);
    }

    // 7) epilogue
    final_kernel<<<(N * CO + 255) / 256, 256>>>(bmu, bls, eps, z, N);
}

// round 2
// speedup vs baseline: 1.8933x; 1.8933x over previous
#include <cuda_runtime.h>
#include <cuda_bf16.h>
#include <math.h>

typedef unsigned long long ull;

#define NMAX 100000
#define EMAX 1600000
#define CIN  128
#define CO   64
#define CH   128   // combined: [0..63]=mu, [64..127]=logstd

// ---------------- scratch (static device globals) --------------------------
__device__ int   g_is64;
__device__ int   g_cnt[NMAX];        // in-degree (excl. self loop)
__device__ int   g_fill[NMAX];       // bucket fill counters
__device__ int   g_rows[NMAX + 1];   // CSR row starts
__device__ int   g_bsum[512];        // scan block sums
__device__ int   g_esrc[EMAX];       // CSR-ordered src indices
__device__ float g_dinv[NMAX];
__device__ float g_h[(size_t)NMAX * CH];   // 51.2 MB

// ---------------- dtype detection: int64 vs int32 edge_index ---------------
__global__ void detect_kernel(const unsigned int* __restrict__ w, int nwords) {
    __shared__ int any;
    if (threadIdx.x == 0) any = 0;
    __syncthreads();
    int local = 0;
    for (int i = 1 + 2 * threadIdx.x; i < nwords; i += 2 * blockDim.x)
        local |= (w[i] != 0u);
    if (local) atomicOr(&any, 1);
    __syncthreads();
    if (threadIdx.x == 0) g_is64 = (any == 0) ? 1 : 0;
}

// ---------------- init counters --------------------------------------------
__global__ void init_kernel(int n_nodes) {
    int i = blockIdx.x * blockDim.x + threadIdx.x;
    if (i < n_nodes) { g_cnt[i] = 0; g_fill[i] = 0; }
}

// ---------------- histogram over dst ---------------------------------------
__global__ void hist_kernel(const void* __restrict__ ei, int E) {
    int e = blockIdx.x * blockDim.x + threadIdx.x;
    if (e >= E) return;
    int d;
    if (g_is64) d = (int)((const long long*)ei)[e + E];
    else        d = ((const int*)ei)[e + E];
    atomicAdd(&g_cnt[d], 1);
}

__global__ void dinv_kernel(int n_nodes) {
    int i = blockIdx.x * blockDim.x + threadIdx.x;
    if (i < n_nodes) g_dinv[i] = rsqrtf((float)g_cnt[i] + 1.0f);
}

// ---------------- 3-phase exclusive scan of g_cnt → g_rows -----------------
__global__ void scan1_kernel(int n_nodes) {
    __shared__ int sh[256];
    int i = blockIdx.x * 256 + threadIdx.x;
    int c = (i < n_nodes) ? g_cnt[i] : 0;
    sh[threadIdx.x] = c;
    __syncthreads();
#pragma unroll
    for (int off = 1; off < 256; off <<= 1) {
        int t = (threadIdx.x >= off) ? sh[threadIdx.x - off] : 0;
        __syncthreads();
        sh[threadIdx.x] += t;
        __syncthreads();
    }
    if (i < n_nodes) g_rows[i] = sh[threadIdx.x] - c;
    if (threadIdx.x == 255) g_bsum[blockIdx.x] = sh[255];
}

__global__ void scan2_kernel(int nblocks) {
    __shared__ int sh[512];
    int t = threadIdx.x;
    int c = (t < nblocks) ? g_bsum[t] : 0;
    sh[t] = c;
    __syncthreads();
#pragma unroll
    for (int off = 1; off < 512; off <<= 1) {
        int v = (t >= off) ? sh[t - off] : 0;
        __syncthreads();
        sh[t] += v;
        __syncthreads();
    }
    if (t < nblocks) g_bsum[t] = sh[t] - c;
}

__global__ void scan3_kernel(int n_nodes, int E) {
    int i = blockIdx.x * 256 + threadIdx.x;
    if (i < n_nodes) g_rows[i] += g_bsum[blockIdx.x];
    if (i == 0) g_rows[n_nodes] = E;
}

// ---------------- bucket edges into CSR order ------------------------------
__global__ void bucket_kernel(const void* __restrict__ ei, int E) {
    int e = blockIdx.x * blockDim.x + threadIdx.x;
    if (e >= E) return;
    int s, d;
    if (g_is64) {
        const long long* p = (const long long*)ei;
        s = (int)p[e];
        d = (int)p[e + E];
    } else {
        const int* p = (const int*)ei;
        s = p[e];
        d = p[e + E];
    }
    int pos = g_rows[d] + atomicAdd(&g_fill[d], 1);
    g_esrc[pos] = s;
}

// ---------------- fused GEMM: h = x @ [W_mu | W_ls], FFMA2 ------------------
// Tile 128x128, K-chunks of 32. 256 threads, each 8x8 via packed f32x2.
__device__ __forceinline__ ull pack2(float a) {
    ull p;
    asm("mov.b64 %0, {%1, %1};" : "=l"(p) : "f"(a));
    return p;
}
__device__ __forceinline__ void fma2(ull& d, ull a, ull b) {
    asm("fma.rn.f32x2 %0, %1, %2, %0;" : "+l"(d) : "l"(a), "l"(b));
}
__device__ __forceinline__ void unpack2(ull p, float& lo, float& hi) {
    asm("mov.b64 {%0, %1}, %2;" : "=f"(lo), "=f"(hi) : "l"(p));
}

__global__ __launch_bounds__(256) void gemm_kernel(
    const float* __restrict__ x,
    const float* __restrict__ Wmu,
    const float* __restrict__ Wls,
    int n_nodes)
{
    __shared__ float xs[128][36];   // padded; 4-word multiple for STS.128
    __shared__ float ws[32][CH];

    int tid = threadIdx.x;
    int tx = tid & 15;   // col group: 8 cols
    int ty = tid >> 4;   // row group: 8 rows
    int brow = blockIdx.x * 128;

    ull acc[8][4];
#pragma unroll
    for (int r = 0; r < 8; r++)
#pragma unroll
        for (int c = 0; c < 4; c++) acc[r][c] = 0ULL;

    for (int kk = 0; kk < CIN; kk += 32) {
        // load x tile: 128x32 floats = 1024 float4
#pragma unroll
        for (int i = 0; i < 4; i++) {
            int f  = i * 256 + tid;
            int r  = f >> 3;
            int c4 = (f & 7) * 4;
            int grow = brow + r;
            float4 v = make_float4(0.f, 0.f, 0.f, 0.f);
            if (grow < n_nodes)
                v = *(const float4*)&x[(size_t)grow * CIN + kk + c4];
            *(float4*)&xs[r][c4] = v;
        }
        // load W tile: 32x128 floats = 1024 float4
#pragma unroll
        for (int i = 0; i < 4; i++) {
            int f    = i * 256 + tid;
            int r    = f >> 5;
            int col0 = (f & 31) * 4;
            int k    = kk + r;
            float4 v;
            if (col0 < CO) v = *(const float4*)&Wmu[k * CO + col0];
            else           v = *(const float4*)&Wls[k * CO + (col0 - CO)];
            *(float4*)&ws[r][col0] = v;
        }
        __syncthreads();

#pragma unroll 8
        for (int k = 0; k < 32; k++) {
            ull aa[8];
#pragma unroll
            for (int r = 0; r < 8; r++) aa[r] = pack2(xs[ty * 8 + r][k]);
            const longlong2* wp = (const longlong2*)&ws[k][tx * 8];
            longlong2 b01 = wp[0];
            longlong2 b23 = wp[1];
            ull bb[4];
            bb[0] = (ull)b01.x; bb[1] = (ull)b01.y;
            bb[2] = (ull)b23.x; bb[3] = (ull)b23.y;
#pragma unroll
            for (int r = 0; r < 8; r++)
#pragma unroll
                for (int c = 0; c < 4; c++)
                    fma2(acc[r][c], aa[r], bb[c]);
        }
        __syncthreads();
    }

    // store h
#pragma unroll
    for (int r = 0; r < 8; r++) {
        int grow = brow + ty * 8 + r;
        if (grow >= n_nodes) continue;
        float o[8];
#pragma unroll
        for (int c = 0; c < 4; c++) unpack2(acc[r][c], o[2 * c], o[2 * c + 1]);
        float* out = &g_h[(size_t)grow * CH + tx * 8];
        *(float4*)out       = make_float4(o[0], o[1], o[2], o[3]);
        *(float4*)(out + 4) = make_float4(o[4], o[5], o[6], o[7]);
    }
}

// ---------------- gather + epilogue: warp per node --------------------------
__global__ __launch_bounds__(256) void gather_kernel(
    const float* __restrict__ bmu,
    const float* __restrict__ bls,
    const float* __restrict__ eps,
    float* __restrict__ z,
    int n_nodes)
{
    int n = (blockIdx.x * blockDim.x + threadIdx.x) >> 5;
    if (n >= n_nodes) return;
    int lane = threadIdx.x & 31;

    int beg = g_rows[n];
    int end = g_rows[n + 1];
    const float4* hp = (const float4*)g_h;

    float4 acc = make_float4(0.f, 0.f, 0.f, 0.f);
    int e = beg;
    for (; e + 1 < end; e += 2) {
        int s0 = g_esrc[e];
        int s1 = g_esrc[e + 1];
        float w0 = g_dinv[s0];
        float w1 = g_dinv[s1];
        float4 h0 = hp[(size_t)s0 * 32 + lane];
        float4 h1 = hp[(size_t)s1 * 32 + lane];
        acc.x = fmaf(h0.x, w0, acc.x); acc.y = fmaf(h0.y, w0, acc.y);
        acc.z = fmaf(h0.z, w0, acc.z); acc.w = fmaf(h0.w, w0, acc.w);
        acc.x = fmaf(h1.x, w1, acc.x); acc.y = fmaf(h1.y, w1, acc.y);
        acc.z = fmaf(h1.z, w1, acc.z); acc.w = fmaf(h1.w, w1, acc.w);
    }
    if (e < end) {
        int s0 = g_esrc[e];
        float w0 = g_dinv[s0];
        float4 h0 = hp[(size_t)s0 * 32 + lane];
        acc.x = fmaf(h0.x, w0, acc.x); acc.y = fmaf(h0.y, w0, acc.y);
        acc.z = fmaf(h0.z, w0, acc.z); acc.w = fmaf(h0.w, w0, acc.w);
    }

    // self-loop + degree norm: out = dinv[n]*acc + h[n]*dinv[n]^2
    float di = g_dinv[n];
    float d2 = di * di;
    float4 hn = hp[(size_t)n * 32 + lane];
    acc.x = fmaf(acc.x, di, hn.x * d2);
    acc.y = fmaf(acc.y, di, hn.y * d2);
    acc.z = fmaf(acc.z, di, hn.z * d2);
    acc.w = fmaf(acc.w, di, hn.w * d2);

    // lanes 16..31 hold logstd channels: add bias, clamp, exp
    if (lane >= 16) {
        int c = lane * 4 - CO;
        float4 bl = *(const float4*)&bls[c];
        acc.x = __expf(fminf(acc.x + bl.x, 10.0f));
        acc.y = __expf(fminf(acc.y + bl.y, 10.0f));
        acc.z = __expf(fminf(acc.z + bl.z, 10.0f));
        acc.w = __expf(fminf(acc.w + bl.w, 10.0f));
    }
    // shuffle exp(logstd) down to the mu lanes
    float ex0 = __shfl_sync(0xffffffffu, acc.x, (lane + 16) & 31);
    float ex1 = __shfl_sync(0xffffffffu, acc.y, (lane + 16) & 31);
    float ex2 = __shfl_sync(0xffffffffu, acc.z, (lane + 16) & 31);
    float ex3 = __shfl_sync(0xffffffffu, acc.w, (lane + 16) & 31);

    if (lane < 16) {
        int c = lane * 4;
        float4 bm = *(const float4*)&bmu[c];
        float4 ep = *(const float4*)&eps[(size_t)n * CO + c];
        float4 zo;
        zo.x = fmaf(ep.x, ex0, acc.x + bm.x);
        zo.y = fmaf(ep.y, ex1, acc.y + bm.y);
        zo.z = fmaf(ep.z, ex2, acc.z + bm.z);
        zo.w = fmaf(ep.w, ex3, acc.w + bm.w);
        *(float4*)&z[(size_t)n * CO + c] = zo;
    }
}

// ---------------------------------------------------------------------------
extern "C" void kernel_launch(void* const* d_in, const int* in_sizes, int n_in,
                              void* d_out, int out_size) {
    const float* x    = (const float*)d_in[0];
    const void*  ei   = (const void*)d_in[1];
    const float* Wmu  = (const float*)d_in[2];
    const float* bmu  = (const float*)d_in[3];
    const float* Wls  = (const float*)d_in[4];
    const float* bls  = (const float*)d_in[5];
    const float* eps  = (const float*)d_in[6];
    float* z = (float*)d_out;

    int N = in_sizes[0] / CIN;   // 100000
    int E = in_sizes[1] / 2;     // 1600000
    int nsb = (N + 255) / 256;   // scan blocks (391)

    detect_kernel<<<1, 256>>>((const unsigned int*)ei, 2048);
    init_kernel<<<nsb, 256>>>(N);
    hist_kernel<<<(E + 255) / 256, 256>>>(ei, E);
    dinv_kernel<<<nsb, 256>>>(N);
    scan1_kernel<<<nsb, 256>>>(N);
    scan2_kernel<<<1, 512>>>(nsb);
    scan3_kernel<<<nsb, 256>>>(N, E);
    bucket_kernel<<<(E + 255) / 256, 256>>>(ei, E);
    gemm_kernel<<<(N + 127) / 128, 256>>>(x, Wmu, Wls, N);
    {
        int warps_per_block = 256 / 32;
        int blocks = (N + warps_per_block - 1) / warps_per_block;
        gather_kernel<<<blocks, 256>>>(bmu, bls, eps, z, N);
    }
}

// round 3
// speedup vs baseline: 2.0285x; 1.0714x over previous
#include <cuda_runtime.h>
#include <cuda_bf16.h>
#include <math.h>

typedef unsigned long long ull;

#define NMAX 100000
#define EMAX 1600000
#define CIN  128
#define CO   64
#define CH   128   // combined: [0..63]=mu, [64..127]=logstd

// ---------------- scratch (static device globals) --------------------------
__device__ int   g_is64;
__device__ int   g_cnt[NMAX];        // in-degree (excl. self loop)
__device__ int   g_fill[NMAX];       // bucket fill counters
__device__ int   g_rows[NMAX + 1];   // CSR row starts
__device__ int   g_bsum[512];        // scan block sums
__device__ int2  g_edge[EMAX];       // CSR-ordered {src, dinv[src] bits}
__device__ float g_dinv[NMAX];
__device__ float g_h[(size_t)NMAX * CH];   // 51.2 MB

// ---------------- dtype detection: int64 vs int32 edge_index ---------------
__global__ void detect_kernel(const unsigned int* __restrict__ w, int nwords) {
    __shared__ int any;
    if (threadIdx.x == 0) any = 0;
    __syncthreads();
    int local = 0;
    for (int i = 1 + 2 * threadIdx.x; i < nwords; i += 2 * blockDim.x)
        local |= (w[i] != 0u);
    if (local) atomicOr(&any, 1);
    __syncthreads();
    if (threadIdx.x == 0) g_is64 = (any == 0) ? 1 : 0;
}

// ---------------- init counters --------------------------------------------
__global__ void init_kernel(int n_nodes) {
    int i = blockIdx.x * blockDim.x + threadIdx.x;
    if (i < n_nodes) { g_cnt[i] = 0; g_fill[i] = 0; }
}

// ---------------- histogram over dst ---------------------------------------
__global__ void hist_kernel(const void* __restrict__ ei, int E) {
    int e = blockIdx.x * blockDim.x + threadIdx.x;
    if (e >= E) return;
    int d;
    if (g_is64) d = (int)((const long long*)ei)[e + E];
    else        d = ((const int*)ei)[e + E];
    atomicAdd(&g_cnt[d], 1);
}

// ---------------- scan phase 1 (+ dinv fused) ------------------------------
__global__ void scan1_kernel(int n_nodes) {
    __shared__ int sh[256];
    int i = blockIdx.x * 256 + threadIdx.x;
    int c = (i < n_nodes) ? g_cnt[i] : 0;
    if (i < n_nodes) g_dinv[i] = rsqrtf((float)c + 1.0f);
    sh[threadIdx.x] = c;
    __syncthreads();
#pragma unroll
    for (int off = 1; off < 256; off <<= 1) {
        int t = (threadIdx.x >= off) ? sh[threadIdx.x - off] : 0;
        __syncthreads();
        sh[threadIdx.x] += t;
        __syncthreads();
    }
    if (i < n_nodes) g_rows[i] = sh[threadIdx.x] - c;
    if (threadIdx.x == 255) g_bsum[blockIdx.x] = sh[255];
}

__global__ void scan2_kernel(int nblocks) {
    __shared__ int sh[512];
    int t = threadIdx.x;
    int c = (t < nblocks) ? g_bsum[t] : 0;
    sh[t] = c;
    __syncthreads();
#pragma unroll
    for (int off = 1; off < 512; off <<= 1) {
        int v = (t >= off) ? sh[t - off] : 0;
        __syncthreads();
        sh[t] += v;
        __syncthreads();
    }
    if (t < nblocks) g_bsum[t] = sh[t] - c;
}

__global__ void scan3_kernel(int n_nodes, int E) {
    int i = blockIdx.x * 256 + threadIdx.x;
    if (i < n_nodes) g_rows[i] += g_bsum[blockIdx.x];
    if (i == 0) g_rows[n_nodes] = E;
}

// ---------------- bucket edges into CSR order (+ pack norm weight) ---------
__global__ void bucket_kernel(const void* __restrict__ ei, int E) {
    int e = blockIdx.x * blockDim.x + threadIdx.x;
    if (e >= E) return;
    int s, d;
    if (g_is64) {
        const long long* p = (const long long*)ei;
        s = (int)p[e];
        d = (int)p[e + E];
    } else {
        const int* p = (const int*)ei;
        s = p[e];
        d = p[e + E];
    }
    int pos = g_rows[d] + atomicAdd(&g_fill[d], 1);
    g_edge[pos] = make_int2(s, __float_as_int(g_dinv[s]));
}

// ---------------- fused GEMM: h = x @ [W_mu | W_ls], FFMA2 ------------------
// 128x128 tile. W resident in smem for whole block. 256 threads, 8x8/thread:
// rows ty*8+0..7, cols {tx*4..tx*4+3} in mu half AND ls half (conflict-free
// LDS.128 b-reads: tx*4 words stride => 32 distinct banks per phase).
__device__ __forceinline__ ull pack2(float a) {
    ull p;
    asm("mov.b64 %0, {%1, %1};" : "=l"(p) : "f"(a));
    return p;
}
__device__ __forceinline__ void fma2(ull& d, ull a, ull b) {
    asm("fma.rn.f32x2 %0, %1, %2, %0;" : "+l"(d) : "l"(a), "l"(b));
}
__device__ __forceinline__ void unpack2(ull p, float& lo, float& hi) {
    asm("mov.b64 {%0, %1}, %2;" : "=f"(lo), "=f"(hi) : "l"(p));
}

#define GEMM_SMEM_FLOATS (128 * 128 + 128 * 36)

__global__ __launch_bounds__(256) void gemm_kernel(
    const float* __restrict__ x,
    const float* __restrict__ Wmu,
    const float* __restrict__ Wls,
    int n_nodes)
{
    extern __shared__ float smem[];
    float* ws = smem;               // [128][128]: [k][0..63]=Wmu, [64..127]=Wls
    float* xs = smem + 128 * 128;   // [128][36]

    int tid = threadIdx.x;
    int tx = tid & 15;
    int ty = tid >> 4;
    int brow = blockIdx.x * 128;

    // load full W once: 4096 float4
#pragma unroll
    for (int i = 0; i < 16; i++) {
        int f  = i * 256 + tid;
        int r  = f >> 5;
        int c0 = (f & 31) * 4;
        float4 v;
        if (c0 < CO) v = *(const float4*)&Wmu[r * CO + c0];
        else         v = *(const float4*)&Wls[r * CO + (c0 - CO)];
        *(float4*)&ws[r * CH + c0] = v;
    }

    ull am[8][2], al[8][2];
#pragma unroll
    for (int r = 0; r < 8; r++) {
        am[r][0] = am[r][1] = 0ULL;
        al[r][0] = al[r][1] = 0ULL;
    }

    for (int kk = 0; kk < CIN; kk += 32) {
        // load x chunk: 128x32 floats = 1024 float4
#pragma unroll
        for (int i = 0; i < 4; i++) {
            int f  = i * 256 + tid;
            int r  = f >> 3;
            int c4 = (f & 7) * 4;
            int grow = brow + r;
            float4 v = make_float4(0.f, 0.f, 0.f, 0.f);
            if (grow < n_nodes)
                v = *(const float4*)&x[(size_t)grow * CIN + kk + c4];
            *(float4*)&xs[r * 36 + c4] = v;
        }
        __syncthreads();

#pragma unroll 8
        for (int k = 0; k < 32; k++) {
            const float* wrow = &ws[(kk + k) * CH];
            longlong2 bm = *(const longlong2*)&wrow[tx * 4];
            longlong2 bl = *(const longlong2*)&wrow[CO + tx * 4];
            ull bm0 = (ull)bm.x, bm1 = (ull)bm.y;
            ull bl0 = (ull)bl.x, bl1 = (ull)bl.y;
#pragma unroll
            for (int r = 0; r < 8; r++) {
                ull aa = pack2(xs[(ty * 8 + r) * 36 + k]);
                fma2(am[r][0], aa, bm0);
                fma2(am[r][1], aa, bm1);
                fma2(al[r][0], aa, bl0);
                fma2(al[r][1], aa, bl1);
            }
        }
        __syncthreads();
    }

    // store h
#pragma unroll
    for (int r = 0; r < 8; r++) {
        int grow = brow + ty * 8 + r;
        if (grow >= n_nodes) continue;
        float4 om, ol;
        unpack2(am[r][0], om.x, om.y);
        unpack2(am[r][1], om.z, om.w);
        unpack2(al[r][0], ol.x, ol.y);
        unpack2(al[r][1], ol.z, ol.w);
        float* out = &g_h[(size_t)grow * CH];
        *(float4*)&out[tx * 4]      = om;
        *(float4*)&out[CO + tx * 4] = ol;
    }
}

// ---------------- gather + epilogue: warp per node --------------------------
__global__ __launch_bounds__(256) void gather_kernel(
    const float* __restrict__ bmu,
    const float* __restrict__ bls,
    const float* __restrict__ eps,
    float* __restrict__ z,
    int n_nodes)
{
    int n = (blockIdx.x * blockDim.x + threadIdx.x) >> 5;
    if (n >= n_nodes) return;
    int lane = threadIdx.x & 31;

    int beg = g_rows[n];
    int end = g_rows[n + 1];
    const float4* hp = (const float4*)g_h;

    float4 acc = make_float4(0.f, 0.f, 0.f, 0.f);
    int e = beg;
    for (; e + 3 < end; e += 4) {
        int2 e0 = g_edge[e];
        int2 e1 = g_edge[e + 1];
        int2 e2 = g_edge[e + 2];
        int2 e3 = g_edge[e + 3];
        float4 h0 = hp[(size_t)e0.x * 32 + lane];
        float4 h1 = hp[(size_t)e1.x * 32 + lane];
        float4 h2 = hp[(size_t)e2.x * 32 + lane];
        float4 h3 = hp[(size_t)e3.x * 32 + lane];
        float w0 = __int_as_float(e0.y), w1 = __int_as_float(e1.y);
        float w2 = __int_as_float(e2.y), w3 = __int_as_float(e3.y);
        acc.x = fmaf(h0.x, w0, acc.x); acc.y = fmaf(h0.y, w0, acc.y);
        acc.z = fmaf(h0.z, w0, acc.z); acc.w = fmaf(h0.w, w0, acc.w);
        acc.x = fmaf(h1.x, w1, acc.x); acc.y = fmaf(h1.y, w1, acc.y);
        acc.z = fmaf(h1.z, w1, acc.z); acc.w = fmaf(h1.w, w1, acc.w);
        acc.x = fmaf(h2.x, w2, acc.x); acc.y = fmaf(h2.y, w2, acc.y);
        acc.z = fmaf(h2.z, w2, acc.z); acc.w = fmaf(h2.w, w2, acc.w);
        acc.x = fmaf(h3.x, w3, acc.x); acc.y = fmaf(h3.y, w3, acc.y);
        acc.z = fmaf(h3.z, w3, acc.z); acc.w = fmaf(h3.w, w3, acc.w);
    }
    for (; e < end; e++) {
        int2 e0 = g_edge[e];
        float w0 = __int_as_float(e0.y);
        float4 h0 = hp[(size_t)e0.x * 32 + lane];
        acc.x = fmaf(h0.x, w0, acc.x); acc.y = fmaf(h0.y, w0, acc.y);
        acc.z = fmaf(h0.z, w0, acc.z); acc.w = fmaf(h0.w, w0, acc.w);
    }

    // self-loop + degree norm: out = dinv[n]*acc + h[n]*dinv[n]^2
    float di = g_dinv[n];
    float d2 = di * di;
    float4 hn = hp[(size_t)n * 32 + lane];
    acc.x = fmaf(acc.x, di, hn.x * d2);
    acc.y = fmaf(acc.y, di, hn.y * d2);
    acc.z = fmaf(acc.z, di, hn.z * d2);
    acc.w = fmaf(acc.w, di, hn.w * d2);

    // lanes 16..31 hold logstd channels: add bias, clamp, exp
    if (lane >= 16) {
        int c = lane * 4 - CO;
        float4 bl = *(const float4*)&bls[c];
        acc.x = __expf(fminf(acc.x + bl.x, 10.0f));
        acc.y = __expf(fminf(acc.y + bl.y, 10.0f));
        acc.z = __expf(fminf(acc.z + bl.z, 10.0f));
        acc.w = __expf(fminf(acc.w + bl.w, 10.0f));
    }
    // shuffle exp(logstd) down to the mu lanes
    float ex0 = __shfl_sync(0xffffffffu, acc.x, (lane + 16) & 31);
    float ex1 = __shfl_sync(0xffffffffu, acc.y, (lane + 16) & 31);
    float ex2 = __shfl_sync(0xffffffffu, acc.z, (lane + 16) & 31);
    float ex3 = __shfl_sync(0xffffffffu, acc.w, (lane + 16) & 31);

    if (lane < 16) {
        int c = lane * 4;
        float4 bm = *(const float4*)&bmu[c];
        float4 ep = *(const float4*)&eps[(size_t)n * CO + c];
        float4 zo;
        zo.x = fmaf(ep.x, ex0, acc.x + bm.x);
        zo.y = fmaf(ep.y, ex1, acc.y + bm.y);
        zo.z = fmaf(ep.z, ex2, acc.z + bm.z);
        zo.w = fmaf(ep.w, ex3, acc.w + bm.w);
        *(float4*)&z[(size_t)n * CO + c] = zo;
    }
}

// ---------------------------------------------------------------------------
extern "C" void kernel_launch(void* const* d_in, const int* in_sizes, int n_in,
                              void* d_out, int out_size) {
    const float* x    = (const float*)d_in[0];
    const void*  ei   = (const void*)d_in[1];
    const float* Wmu  = (const float*)d_in[2];
    const float* bmu  = (const float*)d_in[3];
    const float* Wls  = (const float*)d_in[4];
    const float* bls  = (const float*)d_in[5];
    const float* eps  = (const float*)d_in[6];
    float* z = (float*)d_out;

    int N = in_sizes[0] / CIN;   // 100000
    int E = in_sizes[1] / 2;     // 1600000
    int nsb = (N + 255) / 256;   // scan blocks (391)

    // one-time resources (host-side only; no device allocations)
    static cudaStream_t s2 = nullptr;
    static cudaEvent_t evFork = nullptr, evGemm = nullptr;
    static int smem_set = 0;
    if (s2 == nullptr) {
        cudaStreamCreateWithFlags(&s2, cudaStreamNonBlocking);
        cudaEventCreateWithFlags(&evFork, cudaEventDisableTiming);
        cudaEventCreateWithFlags(&evGemm, cudaEventDisableTiming);
    }
    if (!smem_set) {
        cudaFuncSetAttribute(gemm_kernel,
                             cudaFuncAttributeMaxDynamicSharedMemorySize,
                             GEMM_SMEM_FLOATS * sizeof(float));
        smem_set = 1;
    }

    // fork: GEMM on side stream (depends only on x, W)
    cudaEventRecord(evFork, 0);
    cudaStreamWaitEvent(s2, evFork, 0);
    gemm_kernel<<<(N + 127) / 128, 256, GEMM_SMEM_FLOATS * sizeof(float), s2>>>(
        x, Wmu, Wls, N);
    cudaEventRecord(evGemm, s2);

    // main stream: CSR build
    init_kernel<<<nsb, 256>>>(N);
    detect_kernel<<<1, 256>>>((const unsigned int*)ei, 2048);
    hist_kernel<<<(E + 255) / 256, 256>>>(ei, E);
    scan1_kernel<<<nsb, 256>>>(N);
    scan2_kernel<<<1, 512>>>(nsb);
    scan3_kernel<<<nsb, 256>>>(N, E);
    bucket_kernel<<<(E + 255) / 256, 256>>>(ei, E);

    // join: gather needs both CSR and h
    cudaStreamWaitEvent(0, evGemm, 0);
    {
        int warps_per_block = 256 / 32;
        int blocks = (N + warps_per_block - 1) / warps_per_block;
        gather_kernel<<<blocks, 256>>>(bmu, bls, eps, z, N);
    }
}